// round 2
// baseline (speedup 1.0000x reference)
#include <cuda_runtime.h>
#include <cuda_fp16.h>
#include <cstdint>

// ======================= problem constants =======================

static constexpr int M = 128;
static constexpr int K = 4096;
static constexpr int N = 11008;
static constexpr int NTILE = 64;          // output columns per CTA
static constexpr int KTILE = 64;          // K per pipeline stage
static constexpr int NITER = K / KTILE;   // 64
static constexpr int THREADS = 256;       // 8 warps: 4 (M) x 2 (N)
static constexpr int NBLOCKS = N / NTILE; // 172

// fp16 copy of x, produced by a pre-kernel (allowed: __device__ global scratch)
__device__ __half g_x16[M * K];

// ======================= small helpers =======================

__device__ __forceinline__ uint32_t smem_u32(const void* p) {
    uint32_t a;
    asm("{ .reg .u64 t; cvta.to.shared.u64 t, %1; cvt.u32.u64 %0, t; }"
        : "=r"(a) : "l"(p));
    return a;
}

// SW128 swizzle (Swizzle<3,4,3>): XOR bits [6:4] with bits [9:7]
#define SWZ(x) ((uint32_t)(x) ^ ((((uint32_t)(x)) >> 3) & 0x70u))

#define STS128(smem_addr, r0, r1, r2, r3) \
    asm volatile( \
        "st.shared.v4.b32 [%0], {%1, %2, %3, %4};" \
        :: "r"(smem_addr), "r"(r0), "r"(r1), "r"(r2), "r"(r3) \
        : "memory")

__device__ __forceinline__ void ldsm4(uint32_t (&r)[4], uint32_t addr) {
    asm volatile(
        "ldmatrix.sync.aligned.m8n8.x4.shared.b16 {%0,%1,%2,%3}, [%4];"
        : "=r"(r[0]), "=r"(r[1]), "=r"(r[2]), "=r"(r[3])
        : "r"(addr));
}

__device__ __forceinline__ void mma16816(float (&c)[4], const uint32_t (&a)[4],
                                         uint32_t b0, uint32_t b1) {
    asm volatile(
        "mma.sync.aligned.m16n8k16.row.col.f32.f16.f16.f32 "
        "{%0,%1,%2,%3}, {%4,%5,%6,%7}, {%8,%9}, {%0,%1,%2,%3};"
        : "+f"(c[0]), "+f"(c[1]), "+f"(c[2]), "+f"(c[3])
        : "r"(a[0]), "r"(a[1]), "r"(a[2]), "r"(a[3]), "r"(b0), "r"(b1));
}

// ======================= kernel 0: x fp32 -> fp16 =======================

__global__ void convert_x_kernel(const float* __restrict__ x) {
    int i = blockIdx.x * blockDim.x + threadIdx.x;
    if (i < (M * K) / 4) {
        float4 v = reinterpret_cast<const float4*>(x)[i];
        __half2 a = __floats2half2_rn(v.x, v.y);
        __half2 b = __floats2half2_rn(v.z, v.w);
        reinterpret_cast<__half2*>(g_x16)[2 * i]     = a;
        reinterpret_cast<__half2*>(g_x16)[2 * i + 1] = b;
    }
}

// ======================= kernel 1: fused dequant + GEMM =======================
//
// SMEM A: [128 m][64 k] fp16, 128 B/row, SW128-swizzled, double-buffered (2x16KB)
// SMEM B: [64 n][64 k]  fp16 (B^T, k-contiguous), SW128-swizzled, 2x8KB
// Warp grid 4(M) x 2(N); warp tile 32x32; mma m16n8k16 row.col.

__global__ void __launch_bounds__(THREADS, 2)
quantlinear_kernel(
    const int*   __restrict__ qweight,  // [K/8, N] int32 (8 nibbles along K)
    const int*   __restrict__ qzeros,   // [G, N/8] int32 (8 nibbles along N)
    const float* __restrict__ scales,   // [G, N]
    const float* __restrict__ bias,     // [N]
    float*       __restrict__ out       // [M, N]
) {
    __shared__ __align__(1024) __half smA[2][128 * 64];
    __shared__ __align__(1024) __half smB[2][64 * 64];

    const int tid  = threadIdx.x;
    const int wid  = tid >> 5;
    const int lane = tid & 31;
    const int mw   = wid & 3;   // warp M index (0..3) -> rows mw*32
    const int nw   = wid >> 2;  // warp N index (0..1) -> cols nw*32
    const int n0   = blockIdx.x * NTILE;

    uint32_t aBase[2] = { smem_u32(smA[0]), smem_u32(smA[1]) };
    uint32_t bBase[2] = { smem_u32(smB[0]), smem_u32(smB[1]) };

    // ldmatrix per-thread invariant (unswizzled) byte offsets
    // A x4 tiles: rows m0+ (lane%16), k-half (lane/16)*16B
    const uint32_t aOff0 =
        (uint32_t)((mw * 32 + (lane & 15)) * 128 + (lane >> 4) * 16);
    // B x4 tiles: n rows n0w + 8*(lane/16) + lane%8, k-half ((lane>>3)&1)*16B
    const uint32_t bOff0 =
        (uint32_t)((nw * 32 + ((lane >> 4) << 3) + (lane & 7)) * 128 +
                   ((lane >> 3) & 1) * 16);

    // loader assignment: each thread owns 2 qweight words per stage
    const int lnA = tid >> 3;       // local n (0..31); second word at +32
    const int lkr = tid & 7;        // packed k-row within stage (0..7)
    const int gnA = n0 + lnA;
    const int gnB = gnA + 32;

    float c[2][4][4];
    #pragma unroll
    for (int i = 0; i < 2; ++i)
        #pragma unroll
        for (int j = 0; j < 4; ++j)
            #pragma unroll
            for (int l = 0; l < 4; ++l) c[i][j][l] = 0.f;

    // prefetch registers
    uint4    aPre[4];
    uint32_t bwA = 0, bwB = 0;
    __half2  s2A, z2A, s2B, z2B;

    auto LOAD = [&](int tn) {
        if ((tn & 1) == 0) {  // new quant group every 2 stages (GS=128, KTILE=64)
            const int g = tn >> 1;
            const float sA = scales[(size_t)g * N + gnA];
            const float sB = scales[(size_t)g * N + gnB];
            const uint32_t zwA = (uint32_t)qzeros[(size_t)g * (N / 8) + (gnA >> 3)];
            const uint32_t zwB = (uint32_t)qzeros[(size_t)g * (N / 8) + (gnB >> 3)];
            const uint32_t zA = ((zwA >> ((gnA & 7) * 4)) & 0xFu) + 1u;
            const uint32_t zB = ((zwB >> ((gnB & 7) * 4)) & 0xFu) + 1u;
            s2A = __float2half2_rn(sA);
            s2B = __float2half2_rn(sB);
            uint32_t za = 0x64006400u + zA + (zA << 16);  // fp16x2 (1024+z), exact
            uint32_t zb = 0x64006400u + zB + (zB << 16);
            z2A = *reinterpret_cast<__half2*>(&za);
            z2B = *reinterpret_cast<__half2*>(&zb);
        }
        bwA = (uint32_t)qweight[(size_t)(tn * 8 + lkr) * N + gnA];
        bwB = (uint32_t)qweight[(size_t)(tn * 8 + lkr) * N + gnB];
        #pragma unroll
        for (int i = 0; i < 4; ++i) {
            const int cidx = tid + THREADS * i;   // 0..1023
            const int m  = cidx >> 3;
            const int ck = cidx & 7;
            aPre[i] = *reinterpret_cast<const uint4*>(
                g_x16 + (size_t)m * K + tn * KTILE + ck * 8);
        }
    };

    auto DEQ_STS = [&](int buf) {
        // A tile
        #pragma unroll
        for (int i = 0; i < 4; ++i) {
            const int cidx = tid + THREADS * i;
            const int m  = cidx >> 3;
            const int ck = cidx & 7;
            const uint32_t off = SWZ(m * 128 + ck * 16);
            STS128(aBase[buf] + off, aPre[i].x, aPre[i].y, aPre[i].z, aPre[i].w);
        }
        // B tile: dequant 8 nibbles -> 8 fp16 (16B), two words
        uint32_t r[4];
        #pragma unroll
        for (int i = 0; i < 4; ++i) {
            const uint32_t byte = (bwA >> (8 * i)) & 0xFFu;
            uint32_t qb = 0x64006400u | (byte & 0xFu) | ((byte & 0xF0u) << 12);
            __half2 q2 = *reinterpret_cast<__half2*>(&qb);
            __half2 w2 = __hmul2(__hsub2(q2, z2A), s2A);  // (q-z) exact, then scale
            r[i] = *reinterpret_cast<uint32_t*>(&w2);
        }
        STS128(bBase[buf] + SWZ(lnA * 128 + lkr * 16), r[0], r[1], r[2], r[3]);
        #pragma unroll
        for (int i = 0; i < 4; ++i) {
            const uint32_t byte = (bwB >> (8 * i)) & 0xFFu;
            uint32_t qb = 0x64006400u | (byte & 0xFu) | ((byte & 0xF0u) << 12);
            __half2 q2 = *reinterpret_cast<__half2*>(&qb);
            __half2 w2 = __hmul2(__hsub2(q2, z2B), s2B);
            r[i] = *reinterpret_cast<uint32_t*>(&w2);
        }
        STS128(bBase[buf] + SWZ((lnA + 32) * 128 + lkr * 16), r[0], r[1], r[2], r[3]);
    };

    auto COMPUTE = [&](int buf) {
        #pragma unroll
        for (int ks = 0; ks < 4; ++ks) {
            uint32_t a[2][4], b[2][4];
            const uint32_t akb = (uint32_t)(ks * 32);
            ldsm4(a[0], aBase[buf] + SWZ(aOff0 + akb));
            ldsm4(a[1], aBase[buf] + SWZ(aOff0 + 2048 + akb));   // +16 rows
            ldsm4(b[0], bBase[buf] + SWZ(bOff0 + akb));
            ldsm4(b[1], bBase[buf] + SWZ(bOff0 + 2048 + akb));   // +16 n
            #pragma unroll
            for (int mi = 0; mi < 2; ++mi) {
                #pragma unroll
                for (int p = 0; p < 2; ++p) {
                    mma16816(c[mi][2 * p + 0], a[mi], b[p][0], b[p][1]);
                    mma16816(c[mi][2 * p + 1], a[mi], b[p][2], b[p][3]);
                }
            }
        }
    };

    // -------- pipeline --------
    LOAD(0);
    DEQ_STS(0);
    __syncthreads();

    for (int t = 0; t < NITER; ++t) {
        const int cur = t & 1;
        if (t + 1 < NITER) LOAD(t + 1);        // LDG into regs (latency hidden)
        COMPUTE(cur);                           // ldmatrix + HMMA from buf cur
        if (t + 1 < NITER) DEQ_STS(cur ^ 1);    // fill other buffer
        __syncthreads();
    }

    // -------- epilogue: C + bias --------
    const int q  = lane >> 2;   // 0..7
    const int r2 = lane & 3;    // 0..3
    #pragma unroll
    for (int mi = 0; mi < 2; ++mi) {
        const int row0 = mw * 32 + mi * 16 + q;
        #pragma unroll
        for (int nj = 0; nj < 4; ++nj) {
            const int col = n0 + nw * 32 + nj * 8 + 2 * r2;
            const float2 bv = *reinterpret_cast<const float2*>(bias + col);
            float2 o0, o1;
            o0.x = c[mi][nj][0] + bv.x;
            o0.y = c[mi][nj][1] + bv.y;
            o1.x = c[mi][nj][2] + bv.x;
            o1.y = c[mi][nj][3] + bv.y;
            *reinterpret_cast<float2*>(out + (size_t)row0 * N + col)       = o0;
            *reinterpret_cast<float2*>(out + (size_t)(row0 + 8) * N + col) = o1;
        }
    }
}

// ======================= launch =======================

extern "C" void kernel_launch(void* const* d_in, const int* in_sizes, int n_in,
                              void* d_out, int out_size) {
    const float* x       = (const float*)d_in[0];
    const int*   qweight = (const int*)d_in[1];
    const int*   qzeros  = (const int*)d_in[2];
    const float* scales  = (const float*)d_in[3];
    const float* bias    = (const float*)d_in[4];
    // d_in[5] = g_idx: arange(K)//128 for this problem; group = k/GS hardcoded.
    float* out = (float*)d_out;

    convert_x_kernel<<<(M * K / 4 + 255) / 256, 256>>>(x);
    quantlinear_kernel<<<NBLOCKS, THREADS>>>(qweight, qzeros, scales, bias, out);
}

// round 3
// speedup vs baseline: 1.0810x; 1.0810x over previous
#include <cuda_runtime.h>
#include <cuda_fp16.h>
#include <cstdint>

// ======================= problem constants =======================

static constexpr int M = 128;
static constexpr int K = 4096;
static constexpr int N = 11008;
static constexpr int NTILE = 64;          // output columns per CTA
static constexpr int KTILE = 128;         // K per pipeline stage (== group size)
static constexpr int NITER = K / KTILE;   // 32
static constexpr int THREADS = 256;       // 8 warps: 4 (M) x 2 (N)
static constexpr int NBLOCKS = N / NTILE; // 172

// SMEM layout (dynamic): A: 2 bufs x 2 k-subtiles x 16KB ; B: 2 x 2 x 8KB
static constexpr uint32_t A_BUF_STRIDE = 32768;   // per buffer (2 subtiles)
static constexpr uint32_t A_SUB_STRIDE = 16384;   // 128 m x 64 k fp16
static constexpr uint32_t B_BASE_OFF   = 65536;
static constexpr uint32_t B_BUF_STRIDE = 16384;
static constexpr uint32_t B_SUB_STRIDE = 8192;    // 64 n x 64 k fp16
static constexpr uint32_t SMEM_BYTES   = 98304 + 1024;

// fp16 copy of x, produced by a pre-kernel (allowed: __device__ global scratch)
__device__ __half g_x16[M * K];

// ======================= small helpers =======================

__device__ __forceinline__ uint32_t smem_u32(const void* p) {
    uint32_t a;
    asm("{ .reg .u64 t; cvta.to.shared.u64 t, %1; cvt.u32.u64 %0, t; }"
        : "=r"(a) : "l"(p));
    return a;
}

// SW128 swizzle (Swizzle<3,4,3>): XOR bits [6:4] with bits [9:7]
#define SWZ(x) ((uint32_t)(x) ^ ((((uint32_t)(x)) >> 3) & 0x70u))

#define STS128(smem_addr, r0, r1, r2, r3) \
    asm volatile( \
        "st.shared.v4.b32 [%0], {%1, %2, %3, %4};" \
        :: "r"(smem_addr), "r"(r0), "r"(r1), "r"(r2), "r"(r3) \
        : "memory")

#define CP_ASYNC16(dst, src) \
    asm volatile("cp.async.ca.shared.global [%0], [%1], 16;" \
                 :: "r"(dst), "l"(src) : "memory")

#define CP_COMMIT() asm volatile("cp.async.commit_group;" ::: "memory")
#define CP_WAIT0()  asm volatile("cp.async.wait_group 0;" ::: "memory")

__device__ __forceinline__ void ldsm4(uint32_t (&r)[4], uint32_t addr) {
    asm volatile(
        "ldmatrix.sync.aligned.m8n8.x4.shared.b16 {%0,%1,%2,%3}, [%4];"
        : "=r"(r[0]), "=r"(r[1]), "=r"(r[2]), "=r"(r[3])
        : "r"(addr));
}

__device__ __forceinline__ void mma16816(float (&c)[4], const uint32_t (&a)[4],
                                         uint32_t b0, uint32_t b1) {
    asm volatile(
        "mma.sync.aligned.m16n8k16.row.col.f32.f16.f16.f32 "
        "{%0,%1,%2,%3}, {%4,%5,%6,%7}, {%8,%9}, {%0,%1,%2,%3};"
        : "+f"(c[0]), "+f"(c[1]), "+f"(c[2]), "+f"(c[3])
        : "r"(a[0]), "r"(a[1]), "r"(a[2]), "r"(a[3]), "r"(b0), "r"(b1));
}

// ======================= kernel 0: x fp32 -> fp16 =======================

__global__ void convert_x_kernel(const float* __restrict__ x) {
    int i = blockIdx.x * blockDim.x + threadIdx.x;
    if (i < (M * K) / 4) {
        float4 v = reinterpret_cast<const float4*>(x)[i];
        __half2 a = __floats2half2_rn(v.x, v.y);
        __half2 b = __floats2half2_rn(v.z, v.w);
        reinterpret_cast<__half2*>(g_x16)[2 * i]     = a;
        reinterpret_cast<__half2*>(g_x16)[2 * i + 1] = b;
    }
}

// ======================= kernel 1: fused dequant + GEMM =======================
//
// A: [128 m][128 k] fp16 per stage, stored as two SW128 k-subtiles, cp.async.
// B: [64 n][128 k] fp16 per stage (dequantized), two SW128 k-subtiles.
// Warp grid 4(M) x 2(N); warp tile 32x32; mma m16n8k16 row.col.

__global__ void __launch_bounds__(THREADS, 2)
quantlinear_kernel(
    const int*   __restrict__ qweight,  // [K/8, N] int32 (8 nibbles along K)
    const int*   __restrict__ qzeros,   // [G, N/8] int32 (8 nibbles along N)
    const float* __restrict__ scales,   // [G, N]
    const float* __restrict__ bias,     // [N]
    float*       __restrict__ out       // [M, N]
) {
    extern __shared__ __align__(1024) char smem_raw[];
    const uint32_t sb = (smem_u32(smem_raw) + 1023u) & ~1023u;

    const int tid  = threadIdx.x;
    const int wid  = tid >> 5;
    const int lane = tid & 31;
    const int mw   = wid & 3;   // warp M index (0..3) -> rows mw*32
    const int nw   = wid >> 2;  // warp N index (0..1) -> cols nw*32
    const int n0   = blockIdx.x * NTILE;

    // ldmatrix per-thread invariant (unswizzled) byte offsets within a k-subtile
    const uint32_t aOff0 =
        (uint32_t)((mw * 32 + (lane & 15)) * 128 + (lane >> 4) * 16);
    const uint32_t bOff0 =
        (uint32_t)((nw * 32 + ((lane >> 4) << 3) + (lane & 7)) * 128 +
                   ((lane >> 3) & 1) * 16);

    // B loader assignment: thread owns n column (tid>>2), 4 packed k-rows
    const int lnB = tid >> 2;        // 0..63
    const int krB = tid & 3;         // base packed row; rows krB + 4*j
    const int gn  = n0 + lnB;

    float c[2][4][4];
    #pragma unroll
    for (int i = 0; i < 2; ++i)
        #pragma unroll
        for (int j = 0; j < 4; ++j)
            #pragma unroll
            for (int l = 0; l < 4; ++l) c[i][j][l] = 0.f;

    uint32_t bw[4];
    __half2  s2, z2;

    // ---- stage helpers ----

    auto ISSUE_A = [&](int t, int buf) {
        const uint32_t abase = sb + (uint32_t)buf * A_BUF_STRIDE;
        #pragma unroll
        for (int i = 0; i < 8; ++i) {
            const int cidx = tid + THREADS * i;   // 0..2047
            const int m  = cidx >> 4;
            const int ck = cidx & 15;             // 16B chunk within 256B row
            const uint32_t kk = (uint32_t)(ck >> 3);
            const uint32_t off = SWZ((uint32_t)(m * 128 + (ck & 7) * 16));
            const __half* src = g_x16 + (size_t)m * K + t * KTILE + ck * 8;
            CP_ASYNC16(abase + kk * A_SUB_STRIDE + off, src);
        }
        CP_COMMIT();
    };

    auto LOAD_B = [&](int t) {
        const int g = t;  // GS == KTILE
        const float s = scales[(size_t)g * N + gn];
        const uint32_t zw = (uint32_t)qzeros[(size_t)g * (N / 8) + (gn >> 3)];
        const uint32_t z = ((zw >> ((gn & 7) * 4)) & 0xFu) + 1u;
        s2 = __float2half2_rn(s);
        uint32_t zb = 0x64006400u + z + (z << 16);  // fp16x2 (1024+z), exact
        z2 = *reinterpret_cast<__half2*>(&zb);
        #pragma unroll
        for (int j = 0; j < 4; ++j) {
            const int r = krB + 4 * j;            // packed k-row 0..15
            bw[j] = (uint32_t)qweight[(size_t)(t * 16 + r) * N + gn];
        }
    };

    auto DEQ_STS = [&](int buf) {
        const uint32_t bbase = sb + B_BASE_OFF + (uint32_t)buf * B_BUF_STRIDE;
        #pragma unroll
        for (int j = 0; j < 4; ++j) {
            const int r = krB + 4 * j;
            uint32_t o[4];
            #pragma unroll
            for (int i = 0; i < 4; ++i) {
                const uint32_t byte = (bw[j] >> (8 * i)) & 0xFFu;
                uint32_t qb = 0x64006400u | (byte & 0xFu) | ((byte & 0xF0u) << 12);
                __half2 q2 = *reinterpret_cast<__half2*>(&qb);
                __half2 w2 = __hmul2(__hsub2(q2, z2), s2);  // (q-z) exact
                o[i] = *reinterpret_cast<uint32_t*>(&w2);
            }
            const uint32_t kk = (uint32_t)(r >> 3);
            const uint32_t off = SWZ((uint32_t)(lnB * 128 + (r & 7) * 16));
            STS128(bbase + kk * B_SUB_STRIDE + off, o[0], o[1], o[2], o[3]);
        }
    };

    auto COMPUTE = [&](int buf) {
        const uint32_t abase = sb + (uint32_t)buf * A_BUF_STRIDE;
        const uint32_t bbase = sb + B_BASE_OFF + (uint32_t)buf * B_BUF_STRIDE;
        #pragma unroll
        for (int ks = 0; ks < 8; ++ks) {
            const uint32_t kk  = (uint32_t)(ks >> 2);
            const uint32_t akb = (uint32_t)((ks & 3) * 32);
            uint32_t a[2][4], b[2][4];
            const uint32_t asub = abase + kk * A_SUB_STRIDE;
            const uint32_t bsub = bbase + kk * B_SUB_STRIDE;
            ldsm4(a[0], asub + SWZ(aOff0 + akb));
            ldsm4(a[1], asub + SWZ(aOff0 + 2048 + akb));   // +16 m rows
            ldsm4(b[0], bsub + SWZ(bOff0 + akb));
            ldsm4(b[1], bsub + SWZ(bOff0 + 2048 + akb));   // +16 n cols
            #pragma unroll
            for (int mi = 0; mi < 2; ++mi) {
                #pragma unroll
                for (int p = 0; p < 2; ++p) {
                    mma16816(c[mi][2 * p + 0], a[mi], b[p][0], b[p][1]);
                    mma16816(c[mi][2 * p + 1], a[mi], b[p][2], b[p][3]);
                }
            }
        }
    };

    // -------- pipeline --------
    ISSUE_A(0, 0);
    LOAD_B(0);
    DEQ_STS(0);
    CP_WAIT0();
    __syncthreads();

    for (int t = 0; t < NITER; ++t) {
        const int cur = t & 1;
        if (t + 1 < NITER) {
            ISSUE_A(t + 1, cur ^ 1);   // async fill of other A buffer
            LOAD_B(t + 1);             // LDG latency hidden under MMAs
        }
        COMPUTE(cur);
        if (t + 1 < NITER) DEQ_STS(cur ^ 1);
        CP_WAIT0();
        __syncthreads();
    }

    // -------- epilogue: C + bias --------
    const int q  = lane >> 2;   // 0..7
    const int r2 = lane & 3;    // 0..3
    #pragma unroll
    for (int mi = 0; mi < 2; ++mi) {
        const int row0 = mw * 32 + mi * 16 + q;
        #pragma unroll
        for (int nj = 0; nj < 4; ++nj) {
            const int col = n0 + nw * 32 + nj * 8 + 2 * r2;
            const float2 bv = *reinterpret_cast<const float2*>(bias + col);
            float2 o0, o1;
            o0.x = c[mi][nj][0] + bv.x;
            o0.y = c[mi][nj][1] + bv.y;
            o1.x = c[mi][nj][2] + bv.x;
            o1.y = c[mi][nj][3] + bv.y;
            *reinterpret_cast<float2*>(out + (size_t)row0 * N + col)       = o0;
            *reinterpret_cast<float2*>(out + (size_t)(row0 + 8) * N + col) = o1;
        }
    }
}

// ======================= launch =======================

extern "C" void kernel_launch(void* const* d_in, const int* in_sizes, int n_in,
                              void* d_out, int out_size) {
    const float* x       = (const float*)d_in[0];
    const int*   qweight = (const int*)d_in[1];
    const int*   qzeros  = (const int*)d_in[2];
    const float* scales  = (const float*)d_in[3];
    const float* bias    = (const float*)d_in[4];
    // d_in[5] = g_idx: arange(K)//128 for this problem; group = k/GS hardcoded.
    float* out = (float*)d_out;

    cudaFuncSetAttribute(quantlinear_kernel,
                         cudaFuncAttributeMaxDynamicSharedMemorySize, SMEM_BYTES);

    convert_x_kernel<<<(M * K / 4 + 255) / 256, 256>>>(x);
    quantlinear_kernel<<<NBLOCKS, THREADS, SMEM_BYTES>>>(qweight, qzeros, scales,
                                                         bias, out);
}

// round 4
// speedup vs baseline: 1.2372x; 1.1444x over previous
#include <cuda_runtime.h>
#include <cuda_fp16.h>
#include <cstdint>

// ======================= problem constants =======================

static constexpr int M = 128;
static constexpr int K = 4096;
static constexpr int N = 11008;
static constexpr int MTILE = 64;          // output rows per CTA
static constexpr int NTILE = 64;          // output columns per CTA
static constexpr int KTILE = 128;         // K per pipeline stage (== group size)
static constexpr int NITER = K / KTILE;   // 32
static constexpr int THREADS = 128;       // 4 warps: 2 (M) x 2 (N)
static constexpr int NBLK_N = N / NTILE;  // 172
static constexpr int NBLK_M = M / MTILE;  // 2

// SMEM (dynamic): A: 2 bufs x 2 k-subtiles x 8KB ; B: 2 x 2 x 8KB  = 64KB
static constexpr uint32_t A_SUB_STRIDE = 8192;    // 64 m x 64 k fp16
static constexpr uint32_t A_BUF_STRIDE = 16384;   // per buffer (2 subtiles)
static constexpr uint32_t B_BASE_OFF   = 32768;
static constexpr uint32_t B_SUB_STRIDE = 8192;    // 64 n x 64 k fp16
static constexpr uint32_t B_BUF_STRIDE = 16384;
static constexpr uint32_t SMEM_BYTES   = 65536 + 1024;

// fp16 copy of x, produced by a pre-kernel (allowed: __device__ global scratch)
__device__ __half g_x16[M * K];

// ======================= small helpers =======================

__device__ __forceinline__ uint32_t smem_u32(const void* p) {
    uint32_t a;
    asm("{ .reg .u64 t; cvta.to.shared.u64 t, %1; cvt.u32.u64 %0, t; }"
        : "=r"(a) : "l"(p));
    return a;
}

// SW128 swizzle (Swizzle<3,4,3>): XOR bits [6:4] with bits [9:7]
#define SWZ(x) ((uint32_t)(x) ^ ((((uint32_t)(x)) >> 3) & 0x70u))

#define STS128(smem_addr, r0, r1, r2, r3) \
    asm volatile( \
        "st.shared.v4.b32 [%0], {%1, %2, %3, %4};" \
        :: "r"(smem_addr), "r"(r0), "r"(r1), "r"(r2), "r"(r3) \
        : "memory")

#define CP_ASYNC16(dst, src) \
    asm volatile("cp.async.ca.shared.global [%0], [%1], 16;" \
                 :: "r"(dst), "l"(src) : "memory")

#define CP_COMMIT() asm volatile("cp.async.commit_group;" ::: "memory")
#define CP_WAIT0()  asm volatile("cp.async.wait_group 0;" ::: "memory")

__device__ __forceinline__ void ldsm4(uint32_t (&r)[4], uint32_t addr) {
    asm volatile(
        "ldmatrix.sync.aligned.m8n8.x4.shared.b16 {%0,%1,%2,%3}, [%4];"
        : "=r"(r[0]), "=r"(r[1]), "=r"(r[2]), "=r"(r[3])
        : "r"(addr));
}

__device__ __forceinline__ void mma16816(float (&c)[4], const uint32_t (&a)[4],
                                         uint32_t b0, uint32_t b1) {
    asm volatile(
        "mma.sync.aligned.m16n8k16.row.col.f32.f16.f16.f32 "
        "{%0,%1,%2,%3}, {%4,%5,%6,%7}, {%8,%9}, {%0,%1,%2,%3};"
        : "+f"(c[0]), "+f"(c[1]), "+f"(c[2]), "+f"(c[3])
        : "r"(a[0]), "r"(a[1]), "r"(a[2]), "r"(a[3]), "r"(b0), "r"(b1));
}

// ======================= kernel 0: x fp32 -> fp16 =======================

__global__ void convert_x_kernel(const float* __restrict__ x) {
    int i = blockIdx.x * blockDim.x + threadIdx.x;
    if (i < (M * K) / 4) {
        float4 v = reinterpret_cast<const float4*>(x)[i];
        __half2 a = __floats2half2_rn(v.x, v.y);
        __half2 b = __floats2half2_rn(v.z, v.w);
        reinterpret_cast<__half2*>(g_x16)[2 * i]     = a;
        reinterpret_cast<__half2*>(g_x16)[2 * i + 1] = b;
    }
}

// ======================= kernel 1: fused dequant + GEMM =======================
//
// CTA tile 64(m) x 64(n), 4 warps (2x2), warp tile 32x32, K staged 128.
// A: [64 m][128 k] fp16, two SW128 k-subtiles, filled by cp.async.
// B: [64 n][128 k] fp16 (dequantized in-register), two SW128 k-subtiles.
// Grid 172(n) x 2(m) = 344 CTAs -> single balanced wave at 3 CTAs/SM.

__global__ void __launch_bounds__(THREADS, 3)
quantlinear_kernel(
    const int*   __restrict__ qweight,  // [K/8, N] int32 (8 nibbles along K)
    const int*   __restrict__ qzeros,   // [G, N/8] int32 (8 nibbles along N)
    const float* __restrict__ scales,   // [G, N]
    const float* __restrict__ bias,     // [N]
    float*       __restrict__ out       // [M, N]
) {
    extern __shared__ __align__(1024) char smem_raw[];
    const uint32_t sb = (smem_u32(smem_raw) + 1023u) & ~1023u;

    const int tid  = threadIdx.x;
    const int wid  = tid >> 5;
    const int lane = tid & 31;
    const int mw   = wid & 1;   // warp M index (0..1) -> rows mw*32
    const int nw   = wid >> 1;  // warp N index (0..1) -> cols nw*32
    const int n0   = blockIdx.x * NTILE;
    const int m0   = blockIdx.y * MTILE;

    // ldmatrix per-thread invariant (unswizzled) byte offsets within a k-subtile
    const uint32_t aOff0 =
        (uint32_t)((mw * 32 + (lane & 15)) * 128 + (lane >> 4) * 16);
    const uint32_t bOff0 =
        (uint32_t)((nw * 32 + ((lane >> 4) << 3) + (lane & 7)) * 128 +
                   ((lane >> 3) & 1) * 16);

    // B loader: thread owns n column (tid>>1), 8 packed k-rows (krB + 2*j)
    const int lnB = tid >> 1;        // 0..63
    const int krB = tid & 1;         // base packed row parity
    const int gn  = n0 + lnB;

    float c[2][4][4];
    #pragma unroll
    for (int i = 0; i < 2; ++i)
        #pragma unroll
        for (int j = 0; j < 4; ++j)
            #pragma unroll
            for (int l = 0; l < 4; ++l) c[i][j][l] = 0.f;

    uint32_t bw[8];
    __half2  s2, z2;

    // ---- stage helpers ----

    auto ISSUE_A = [&](int t, int buf) {
        const uint32_t abase = sb + (uint32_t)buf * A_BUF_STRIDE;
        #pragma unroll
        for (int i = 0; i < 8; ++i) {
            const int cidx = tid + THREADS * i;   // 0..1023
            const int m  = cidx >> 4;             // 0..63
            const int ck = cidx & 15;             // 16B chunk within 256B of k
            const uint32_t kk = (uint32_t)(ck >> 3);
            const uint32_t off = SWZ((uint32_t)(m * 128 + (ck & 7) * 16));
            const __half* src = g_x16 + (size_t)(m0 + m) * K + t * KTILE + ck * 8;
            CP_ASYNC16(abase + kk * A_SUB_STRIDE + off, src);
        }
        CP_COMMIT();
    };

    auto LOAD_B = [&](int t) {
        const int g = t;  // GS == KTILE
        const float s = scales[(size_t)g * N + gn];
        const uint32_t zw = (uint32_t)qzeros[(size_t)g * (N / 8) + (gn >> 3)];
        const uint32_t z = ((zw >> ((gn & 7) * 4)) & 0xFu) + 1u;
        s2 = __float2half2_rn(s);
        uint32_t zb = 0x64006400u + z + (z << 16);  // fp16x2 (1024+z), exact
        z2 = *reinterpret_cast<__half2*>(&zb);
        #pragma unroll
        for (int j = 0; j < 8; ++j) {
            const int r = krB + 2 * j;            // packed k-row 0..15
            bw[j] = (uint32_t)qweight[(size_t)(t * 16 + r) * N + gn];
        }
    };

    auto DEQ_STS = [&](int buf) {
        const uint32_t bbase = sb + B_BASE_OFF + (uint32_t)buf * B_BUF_STRIDE;
        #pragma unroll
        for (int j = 0; j < 8; ++j) {
            const int r = krB + 2 * j;
            uint32_t o[4];
            #pragma unroll
            for (int i = 0; i < 4; ++i) {
                const uint32_t byte = (bw[j] >> (8 * i)) & 0xFFu;
                uint32_t qb = 0x64006400u | (byte & 0xFu) | ((byte & 0xF0u) << 12);
                __half2 q2 = *reinterpret_cast<__half2*>(&qb);
                __half2 w2 = __hmul2(__hsub2(q2, z2), s2);  // (q-z) exact
                o[i] = *reinterpret_cast<uint32_t*>(&w2);
            }
            const uint32_t kk = (uint32_t)(r >> 3);
            const uint32_t off = SWZ((uint32_t)(lnB * 128 + (r & 7) * 16));
            STS128(bbase + kk * B_SUB_STRIDE + off, o[0], o[1], o[2], o[3]);
        }
    };

    auto COMPUTE = [&](int buf) {
        const uint32_t abase = sb + (uint32_t)buf * A_BUF_STRIDE;
        const uint32_t bbase = sb + B_BASE_OFF + (uint32_t)buf * B_BUF_STRIDE;
        #pragma unroll
        for (int ks = 0; ks < 8; ++ks) {
            const uint32_t kk  = (uint32_t)(ks >> 2);
            const uint32_t akb = (uint32_t)((ks & 3) * 32);
            uint32_t a[2][4], b[2][4];
            const uint32_t asub = abase + kk * A_SUB_STRIDE;
            const uint32_t bsub = bbase + kk * B_SUB_STRIDE;
            ldsm4(a[0], asub + SWZ(aOff0 + akb));
            ldsm4(a[1], asub + SWZ(aOff0 + 2048 + akb));   // +16 m rows
            ldsm4(b[0], bsub + SWZ(bOff0 + akb));
            ldsm4(b[1], bsub + SWZ(bOff0 + 2048 + akb));   // +16 n cols
            #pragma unroll
            for (int mi = 0; mi < 2; ++mi) {
                #pragma unroll
                for (int p = 0; p < 2; ++p) {
                    mma16816(c[mi][2 * p + 0], a[mi], b[p][0], b[p][1]);
                    mma16816(c[mi][2 * p + 1], a[mi], b[p][2], b[p][3]);
                }
            }
        }
    };

    // -------- pipeline --------
    ISSUE_A(0, 0);
    LOAD_B(0);
    DEQ_STS(0);
    CP_WAIT0();
    __syncthreads();

    for (int t = 0; t < NITER; ++t) {
        const int cur = t & 1;
        if (t + 1 < NITER) {
            ISSUE_A(t + 1, cur ^ 1);   // async fill of other A buffer
            LOAD_B(t + 1);             // LDG latency hidden under MMAs
        }
        COMPUTE(cur);
        if (t + 1 < NITER) DEQ_STS(cur ^ 1);
        CP_WAIT0();
        __syncthreads();
    }

    // -------- epilogue: C + bias --------
    const int q  = lane >> 2;   // 0..7
    const int r2 = lane & 3;    // 0..3
    #pragma unroll
    for (int mi = 0; mi < 2; ++mi) {
        const int row0 = m0 + mw * 32 + mi * 16 + q;
        #pragma unroll
        for (int nj = 0; nj < 4; ++nj) {
            const int col = n0 + nw * 32 + nj * 8 + 2 * r2;
            const float2 bv = *reinterpret_cast<const float2*>(bias + col);
            float2 o0, o1;
            o0.x = c[mi][nj][0] + bv.x;
            o0.y = c[mi][nj][1] + bv.y;
            o1.x = c[mi][nj][2] + bv.x;
            o1.y = c[mi][nj][3] + bv.y;
            *reinterpret_cast<float2*>(out + (size_t)row0 * N + col)       = o0;
            *reinterpret_cast<float2*>(out + (size_t)(row0 + 8) * N + col) = o1;
        }
    }
}

// ======================= launch =======================

extern "C" void kernel_launch(void* const* d_in, const int* in_sizes, int n_in,
                              void* d_out, int out_size) {
    const float* x       = (const float*)d_in[0];
    const int*   qweight = (const int*)d_in[1];
    const int*   qzeros  = (const int*)d_in[2];
    const float* scales  = (const float*)d_in[3];
    const float* bias    = (const float*)d_in[4];
    // d_in[5] = g_idx: arange(K)//128 for this problem; group = k/GS hardcoded.
    float* out = (float*)d_out;

    cudaFuncSetAttribute(quantlinear_kernel,
                         cudaFuncAttributeMaxDynamicSharedMemorySize, SMEM_BYTES);

    convert_x_kernel<<<(M * K / 4 + 255) / 256, 256>>>(x);
    dim3 grid(NBLK_N, NBLK_M);
    quantlinear_kernel<<<grid, THREADS, SMEM_BYTES>>>(qweight, qzeros, scales,
                                                      bias, out);
}

// round 5
// speedup vs baseline: 1.2818x; 1.0360x over previous
#include <cuda_runtime.h>
#include <cuda_fp16.h>
#include <cstdint>

// ======================= problem constants =======================

static constexpr int M = 128;
static constexpr int K = 4096;
static constexpr int N = 11008;
static constexpr int MTILE = 64;
static constexpr int NTILE = 64;
static constexpr int KTILE = 64;            // K per pipeline stage
static constexpr int KSPLIT = 2;            // K halves -> separate CTAs
static constexpr int KPER = K / KSPLIT;     // 2048 per CTA
static constexpr int NITER = KPER / KTILE;  // 32 stages
static constexpr int THREADS = 128;         // 4 warps: 2 (M) x 2 (N)
static constexpr int NBLK_N = N / NTILE;    // 172
static constexpr int NBLK_M = M / MTILE;    // 2

// SMEM (dynamic): A: 2 bufs x 8KB ; B: 2 bufs x 8KB = 32KB
static constexpr uint32_t A_BUF_STRIDE = 8192;    // 64 m x 64 k fp16
static constexpr uint32_t B_BASE_OFF   = 16384;
static constexpr uint32_t B_BUF_STRIDE = 8192;    // 64 n x 64 k fp16
static constexpr uint32_t SMEM_BYTES   = 32768 + 1024;

// fp16 copy of x, produced by a pre-kernel (allowed: __device__ global scratch)
__device__ __half g_x16[M * K];

// ======================= small helpers =======================

__device__ __forceinline__ uint32_t smem_u32(const void* p) {
    uint32_t a;
    asm("{ .reg .u64 t; cvta.to.shared.u64 t, %1; cvt.u32.u64 %0, t; }"
        : "=r"(a) : "l"(p));
    return a;
}

// SW128 swizzle (Swizzle<3,4,3>): XOR bits [6:4] with bits [9:7]
#define SWZ(x) ((uint32_t)(x) ^ ((((uint32_t)(x)) >> 3) & 0x70u))

#define STS128(smem_addr, r0, r1, r2, r3) \
    asm volatile( \
        "st.shared.v4.b32 [%0], {%1, %2, %3, %4};" \
        :: "r"(smem_addr), "r"(r0), "r"(r1), "r"(r2), "r"(r3) \
        : "memory")

#define CP_ASYNC16(dst, src) \
    asm volatile("cp.async.ca.shared.global [%0], [%1], 16;" \
                 :: "r"(dst), "l"(src) : "memory")

#define CP_COMMIT() asm volatile("cp.async.commit_group;" ::: "memory")
#define CP_WAIT0()  asm volatile("cp.async.wait_group 0;" ::: "memory")

__device__ __forceinline__ void ldsm4(uint32_t (&r)[4], uint32_t addr) {
    asm volatile(
        "ldmatrix.sync.aligned.m8n8.x4.shared.b16 {%0,%1,%2,%3}, [%4];"
        : "=r"(r[0]), "=r"(r[1]), "=r"(r[2]), "=r"(r[3])
        : "r"(addr));
}

__device__ __forceinline__ void mma16816(float (&c)[4], const uint32_t (&a)[4],
                                         uint32_t b0, uint32_t b1) {
    asm volatile(
        "mma.sync.aligned.m16n8k16.row.col.f32.f16.f16.f32 "
        "{%0,%1,%2,%3}, {%4,%5,%6,%7}, {%8,%9}, {%0,%1,%2,%3};"
        : "+f"(c[0]), "+f"(c[1]), "+f"(c[2]), "+f"(c[3])
        : "r"(a[0]), "r"(a[1]), "r"(a[2]), "r"(a[3]), "r"(b0), "r"(b1));
}

// ======================= kernel 0: x fp32 -> fp16 =======================

__global__ void convert_x_kernel(const float* __restrict__ x) {
    int i = blockIdx.x * blockDim.x + threadIdx.x;
    if (i < (M * K) / 4) {
        float4 v = reinterpret_cast<const float4*>(x)[i];
        __half2 a = __floats2half2_rn(v.x, v.y);
        __half2 b = __floats2half2_rn(v.z, v.w);
        reinterpret_cast<__half2*>(g_x16)[2 * i]     = a;
        reinterpret_cast<__half2*>(g_x16)[2 * i + 1] = b;
    }
}

// ======================= kernel 0b: out = broadcast(bias) =======================

__global__ void init_out_kernel(const float* __restrict__ bias,
                                float* __restrict__ out) {
    const int col4 = blockIdx.x * blockDim.x + threadIdx.x;
    if (col4 < N / 4) {
        const float4 b = reinterpret_cast<const float4*>(bias)[col4];
        reinterpret_cast<float4*>(out)[(size_t)blockIdx.y * (N / 4) + col4] = b;
    }
}

// ======================= kernel 1: fused dequant + GEMM (K-split) =======================
//
// CTA tile 64(m) x 64(n) x 2048(k), 4 warps (2x2), warp tile 32x32.
// A: [64 m][64 k] fp16 SW128, cp.async, double-buffered.
// B: [64 n][64 k] fp16 SW128, register-dequantized, double-buffered.
// Grid 172(n) x 2(m) x 2(k) = 688 CTAs; epilogue accumulates via atomicAdd
// onto out preinitialized with bias.

__global__ void __launch_bounds__(THREADS, 4)
quantlinear_kernel(
    const int*   __restrict__ qweight,  // [K/8, N] int32 (8 nibbles along K)
    const int*   __restrict__ qzeros,   // [G, N/8] int32 (8 nibbles along N)
    const float* __restrict__ scales,   // [G, N]
    float*       __restrict__ out       // [M, N], preloaded with bias
) {
    extern __shared__ __align__(1024) char smem_raw[];
    const uint32_t sb = (smem_u32(smem_raw) + 1023u) & ~1023u;

    const int tid  = threadIdx.x;
    const int wid  = tid >> 5;
    const int lane = tid & 31;
    const int mw   = wid & 1;   // warp M index (0..1) -> rows mw*32
    const int nw   = wid >> 1;  // warp N index (0..1) -> cols nw*32
    const int n0   = blockIdx.x * NTILE;
    const int m0   = blockIdx.y * MTILE;
    const int kz   = blockIdx.z;            // K half
    const int qrow0 = kz * (KPER / 8);      // first packed qweight row
    const int g0    = kz * (KPER / 128);    // first quant group

    // ldmatrix per-thread invariant (unswizzled) byte offsets
    const uint32_t aOff0 =
        (uint32_t)((mw * 32 + (lane & 15)) * 128 + (lane >> 4) * 16);
    const uint32_t bOff0 =
        (uint32_t)((nw * 32 + ((lane >> 4) << 3) + (lane & 7)) * 128 +
                   ((lane >> 3) & 1) * 16);

    // B loader: thread owns n column (tid>>1), 4 packed k-rows (krB + 2*j)
    const int lnB = tid >> 1;        // 0..63
    const int krB = tid & 1;
    const int gn  = n0 + lnB;

    float c[2][4][4];
    #pragma unroll
    for (int i = 0; i < 2; ++i)
        #pragma unroll
        for (int j = 0; j < 4; ++j)
            #pragma unroll
            for (int l = 0; l < 4; ++l) c[i][j][l] = 0.f;

    uint32_t bw[4];
    __half2  s2, z2;

    // ---- stage helpers ----

    auto ISSUE_A = [&](int t, int buf) {
        const uint32_t abase = sb + (uint32_t)buf * A_BUF_STRIDE;
        const int kbase = kz * KPER + t * KTILE;
        #pragma unroll
        for (int i = 0; i < 4; ++i) {
            const int cidx = tid + THREADS * i;   // 0..511
            const int m  = cidx >> 3;             // 0..63
            const int ck = cidx & 7;              // 16B chunk in 128B row
            const uint32_t off = SWZ((uint32_t)(m * 128 + ck * 16));
            const __half* src = g_x16 + (size_t)(m0 + m) * K + kbase + ck * 8;
            CP_ASYNC16(abase + off, src);
        }
        CP_COMMIT();
    };

    auto LOAD_B = [&](int t) {
        if ((t & 1) == 0) {   // new quant group every 2 stages (GS=128)
            const int g = g0 + (t >> 1);
            const float s = scales[(size_t)g * N + gn];
            const uint32_t zw = (uint32_t)qzeros[(size_t)g * (N / 8) + (gn >> 3)];
            const uint32_t z = ((zw >> ((gn & 7) * 4)) & 0xFu) + 1u;
            s2 = __float2half2_rn(s);
            uint32_t zb = 0x64006400u + z + (z << 16);  // fp16x2 (1024+z), exact
            z2 = *reinterpret_cast<__half2*>(&zb);
        }
        #pragma unroll
        for (int j = 0; j < 4; ++j) {
            const int r = krB + 2 * j;            // packed k-row 0..7
            bw[j] = (uint32_t)qweight[(size_t)(qrow0 + t * 8 + r) * N + gn];
        }
    };

    auto DEQ_STS = [&](int buf) {
        const uint32_t bbase = sb + B_BASE_OFF + (uint32_t)buf * B_BUF_STRIDE;
        #pragma unroll
        for (int j = 0; j < 4; ++j) {
            const int r = krB + 2 * j;
            uint32_t o[4];
            #pragma unroll
            for (int i = 0; i < 4; ++i) {
                const uint32_t byte = (bw[j] >> (8 * i)) & 0xFFu;
                uint32_t qb = 0x64006400u | (byte & 0xFu) | ((byte & 0xF0u) << 12);
                __half2 q2 = *reinterpret_cast<__half2*>(&qb);
                __half2 w2 = __hmul2(__hsub2(q2, z2), s2);  // (q-z) exact
                o[i] = *reinterpret_cast<uint32_t*>(&w2);
            }
            const uint32_t off = SWZ((uint32_t)(lnB * 128 + r * 16));
            STS128(bbase + off, o[0], o[1], o[2], o[3]);
        }
    };

    auto COMPUTE = [&](int buf) {
        const uint32_t abase = sb + (uint32_t)buf * A_BUF_STRIDE;
        const uint32_t bbase = sb + B_BASE_OFF + (uint32_t)buf * B_BUF_STRIDE;
        #pragma unroll
        for (int ks = 0; ks < 4; ++ks) {
            const uint32_t akb = (uint32_t)(ks * 32);
            uint32_t a[2][4], b[2][4];
            ldsm4(a[0], abase + SWZ(aOff0 + akb));
            ldsm4(a[1], abase + SWZ(aOff0 + 2048 + akb));   // +16 m rows
            ldsm4(b[0], bbase + SWZ(bOff0 + akb));
            ldsm4(b[1], bbase + SWZ(bOff0 + 2048 + akb));   // +16 n cols
            #pragma unroll
            for (int mi = 0; mi < 2; ++mi) {
                #pragma unroll
                for (int p = 0; p < 2; ++p) {
                    mma16816(c[mi][2 * p + 0], a[mi], b[p][0], b[p][1]);
                    mma16816(c[mi][2 * p + 1], a[mi], b[p][2], b[p][3]);
                }
            }
        }
    };

    // -------- pipeline --------
    ISSUE_A(0, 0);
    LOAD_B(0);
    DEQ_STS(0);
    CP_WAIT0();
    __syncthreads();

    for (int t = 0; t < NITER; ++t) {
        const int cur = t & 1;
        if (t + 1 < NITER) {
            ISSUE_A(t + 1, cur ^ 1);
            LOAD_B(t + 1);
        }
        COMPUTE(cur);
        if (t + 1 < NITER) DEQ_STS(cur ^ 1);
        CP_WAIT0();
        __syncthreads();
    }

    // -------- epilogue: atomic accumulate into out (bias preloaded) --------
    const int q  = lane >> 2;   // 0..7
    const int r2 = lane & 3;    // 0..3
    #pragma unroll
    for (int mi = 0; mi < 2; ++mi) {
        const int row0 = m0 + mw * 32 + mi * 16 + q;
        #pragma unroll
        for (int nj = 0; nj < 4; ++nj) {
            const int col = n0 + nw * 32 + nj * 8 + 2 * r2;
            float* p0 = out + (size_t)row0 * N + col;
            float* p1 = out + (size_t)(row0 + 8) * N + col;
            atomicAdd(p0,     c[mi][nj][0]);
            atomicAdd(p0 + 1, c[mi][nj][1]);
            atomicAdd(p1,     c[mi][nj][2]);
            atomicAdd(p1 + 1, c[mi][nj][3]);
        }
    }
}

// ======================= launch =======================

extern "C" void kernel_launch(void* const* d_in, const int* in_sizes, int n_in,
                              void* d_out, int out_size) {
    const float* x       = (const float*)d_in[0];
    const int*   qweight = (const int*)d_in[1];
    const int*   qzeros  = (const int*)d_in[2];
    const float* scales  = (const float*)d_in[3];
    const float* bias    = (const float*)d_in[4];
    // d_in[5] = g_idx: arange(K)//128 for this problem; group = k/GS hardcoded.
    float* out = (float*)d_out;

    cudaFuncSetAttribute(quantlinear_kernel,
                         cudaFuncAttributeMaxDynamicSharedMemorySize, SMEM_BYTES);

    convert_x_kernel<<<(M * K / 4 + 255) / 256, 256>>>(x);
    {
        dim3 gi((N / 4 + 255) / 256, M);
        init_out_kernel<<<gi, 256>>>(bias, out);
    }
    dim3 grid(NBLK_N, NBLK_M, KSPLIT);
    quantlinear_kernel<<<grid, THREADS, SMEM_BYTES>>>(qweight, qzeros, scales, out);
}

// round 6
// speedup vs baseline: 1.3269x; 1.0352x over previous
#include <cuda_runtime.h>
#include <cuda_fp16.h>
#include <cstdint>

// ======================= problem constants =======================

static constexpr int M = 128;
static constexpr int K = 4096;
static constexpr int N = 11008;
static constexpr int MTILE = 64;
static constexpr int NTILE = 64;
static constexpr int KTILE = 64;            // K per pipeline stage
static constexpr int KSPLIT = 4;            // K quarters -> separate CTAs
static constexpr int KPER = K / KSPLIT;     // 1024 per CTA
static constexpr int NITER = KPER / KTILE;  // 16 stages
static constexpr int THREADS = 128;         // 4 warps: 2 (M) x 2 (N)
static constexpr int NBLK_N = N / NTILE;    // 172
static constexpr int NBLK_M = M / MTILE;    // 2

// SMEM (dynamic): A: 2 bufs x 8KB ; B: 2 bufs x 8KB = 32KB
static constexpr uint32_t A_BUF_STRIDE = 8192;    // 64 m x 64 k fp16
static constexpr uint32_t B_BASE_OFF   = 16384;
static constexpr uint32_t B_BUF_STRIDE = 8192;    // 64 n x 64 k fp16
static constexpr uint32_t SMEM_BYTES   = 32768 + 1024;

// fp16 copy of x with k-chunk permutation {0,4,1,5,2,6,3,7} baked in
// (matches the lop3 dual-nibble extraction order of the B dequant path).
__device__ __half g_x16[M * K];

// ======================= small helpers =======================

__device__ __forceinline__ uint32_t smem_u32(const void* p) {
    uint32_t a;
    asm("{ .reg .u64 t; cvta.to.shared.u64 t, %1; cvt.u32.u64 %0, t; }"
        : "=r"(a) : "l"(p));
    return a;
}

// SW128 swizzle (Swizzle<3,4,3>): XOR bits [6:4] with bits [9:7]
#define SWZ(x) ((uint32_t)(x) ^ ((((uint32_t)(x)) >> 3) & 0x70u))

#define STS128(smem_addr, r0, r1, r2, r3) \
    asm volatile( \
        "st.shared.v4.b32 [%0], {%1, %2, %3, %4};" \
        :: "r"(smem_addr), "r"(r0), "r"(r1), "r"(r2), "r"(r3) \
        : "memory")

#define CP_ASYNC16(dst, src) \
    asm volatile("cp.async.ca.shared.global [%0], [%1], 16;" \
                 :: "r"(dst), "l"(src) : "memory")

#define CP_COMMIT() asm volatile("cp.async.commit_group;" ::: "memory")
#define CP_WAIT0()  asm volatile("cp.async.wait_group 0;" ::: "memory")

// d = (a & 0x000F000F) | 0x64006400  -> fp16x2 (1024+q_lo, 1024+q_hi)
__device__ __forceinline__ uint32_t lop3_nib(uint32_t a) {
    uint32_t d;
    asm("lop3.b32 %0, %1, 0x000F000F, 0x64006400, 0xEA;" : "=r"(d) : "r"(a));
    return d;
}

__device__ __forceinline__ void ldsm4(uint32_t (&r)[4], uint32_t addr) {
    asm volatile(
        "ldmatrix.sync.aligned.m8n8.x4.shared.b16 {%0,%1,%2,%3}, [%4];"
        : "=r"(r[0]), "=r"(r[1]), "=r"(r[2]), "=r"(r[3])
        : "r"(addr));
}

__device__ __forceinline__ void mma16816(float (&c)[4], const uint32_t (&a)[4],
                                         uint32_t b0, uint32_t b1) {
    asm volatile(
        "mma.sync.aligned.m16n8k16.row.col.f32.f16.f16.f32 "
        "{%0,%1,%2,%3}, {%4,%5,%6,%7}, {%8,%9}, {%0,%1,%2,%3};"
        : "+f"(c[0]), "+f"(c[1]), "+f"(c[2]), "+f"(c[3])
        : "r"(a[0]), "r"(a[1]), "r"(a[2]), "r"(a[3]), "r"(b0), "r"(b1));
}

// ======================= kernel 0: x fp32 -> fp16, k-permuted =======================
// position j within each 8-k chunk holds original k = {0,4,1,5,2,6,3,7}[j]

__global__ void convert_x_kernel(const float* __restrict__ x) {
    int idx = blockIdx.x * blockDim.x + threadIdx.x;   // chunk index
    if (idx < (M * K) / 8) {
        const float* s = x + (size_t)idx * 8;
        uint4 o;
        __half2* o2 = reinterpret_cast<__half2*>(&o);
        o2[0] = __floats2half2_rn(s[0], s[4]);
        o2[1] = __floats2half2_rn(s[1], s[5]);
        o2[2] = __floats2half2_rn(s[2], s[6]);
        o2[3] = __floats2half2_rn(s[3], s[7]);
        reinterpret_cast<uint4*>(g_x16)[idx] = o;
    }
}

// ======================= kernel 0b: out = broadcast(bias) =======================

__global__ void init_out_kernel(const float* __restrict__ bias,
                                float* __restrict__ out) {
    const int col4 = blockIdx.x * blockDim.x + threadIdx.x;
    if (col4 < N / 4) {
        const float4 b = reinterpret_cast<const float4*>(bias)[col4];
        reinterpret_cast<float4*>(out)[(size_t)blockIdx.y * (N / 4) + col4] = b;
    }
}

// ======================= kernel 1: fused dequant + GEMM (K-split x4) =======================
//
// CTA tile 64(m) x 64(n) x 1024(k), 4 warps (2x2), warp tile 32x32.
// A: [64 m][64 k] fp16 SW128 (k-permuted), cp.async, double-buffered.
// B: [64 n][64 k] fp16 SW128, lop3-dequantized in-register, double-buffered.
// Grid 172 x 2 x 4 = 1376 CTAs; epilogue accumulates via atomicAdd onto
// out preinitialized with bias.

__global__ void __launch_bounds__(THREADS, 4)
quantlinear_kernel(
    const int*   __restrict__ qweight,  // [K/8, N] int32 (8 nibbles along K)
    const int*   __restrict__ qzeros,   // [G, N/8] int32 (8 nibbles along N)
    const float* __restrict__ scales,   // [G, N]
    float*       __restrict__ out       // [M, N], preloaded with bias
) {
    extern __shared__ __align__(1024) char smem_raw[];
    const uint32_t sb = (smem_u32(smem_raw) + 1023u) & ~1023u;

    const int tid  = threadIdx.x;
    const int wid  = tid >> 5;
    const int lane = tid & 31;
    const int mw   = wid & 1;   // warp M index (0..1) -> rows mw*32
    const int nw   = wid >> 1;  // warp N index (0..1) -> cols nw*32
    const int n0   = blockIdx.x * NTILE;
    const int m0   = blockIdx.y * MTILE;
    const int kz   = blockIdx.z;             // K quarter
    const int qrow0 = kz * (KPER / 8);       // first packed qweight row
    const int g0    = kz * (KPER / 128);     // first quant group

    // ldmatrix per-thread invariant (unswizzled) byte offsets
    const uint32_t aOff0 =
        (uint32_t)((mw * 32 + (lane & 15)) * 128 + (lane >> 4) * 16);
    const uint32_t bOff0 =
        (uint32_t)((nw * 32 + ((lane >> 4) << 3) + (lane & 7)) * 128 +
                   ((lane >> 3) & 1) * 16);

    // B loader: thread owns n column (tid>>1), 4 packed k-rows (krB + 2*j)
    const int lnB = tid >> 1;        // 0..63
    const int krB = tid & 1;
    const int gn  = n0 + lnB;

    float c[2][4][4];
    #pragma unroll
    for (int i = 0; i < 2; ++i)
        #pragma unroll
        for (int j = 0; j < 4; ++j)
            #pragma unroll
            for (int l = 0; l < 4; ++l) c[i][j][l] = 0.f;

    uint32_t bw[4];
    __half2  s2, z2;

    // ---- stage helpers ----

    auto ISSUE_A = [&](int t, int buf) {
        const uint32_t abase = sb + (uint32_t)buf * A_BUF_STRIDE;
        const int kbase = kz * KPER + t * KTILE;
        #pragma unroll
        for (int i = 0; i < 4; ++i) {
            const int cidx = tid + THREADS * i;   // 0..511
            const int m  = cidx >> 3;             // 0..63
            const int ck = cidx & 7;              // 16B chunk in 128B row
            const uint32_t off = SWZ((uint32_t)(m * 128 + ck * 16));
            const __half* src = g_x16 + (size_t)(m0 + m) * K + kbase + ck * 8;
            CP_ASYNC16(abase + off, src);
        }
        CP_COMMIT();
    };

    auto LOAD_B = [&](int t) {
        if ((t & 1) == 0) {   // new quant group every 2 stages (GS=128)
            const int g = g0 + (t >> 1);
            const float s = scales[(size_t)g * N + gn];
            const uint32_t zw = (uint32_t)qzeros[(size_t)g * (N / 8) + (gn >> 3)];
            const uint32_t z = ((zw >> ((gn & 7) * 4)) & 0xFu) + 1u;
            s2 = __float2half2_rn(s);
            uint32_t zb = 0x64006400u + z + (z << 16);  // fp16x2 (1024+z), exact
            z2 = *reinterpret_cast<__half2*>(&zb);
        }
        #pragma unroll
        for (int j = 0; j < 4; ++j) {
            const int r = krB + 2 * j;            // packed k-row 0..7
            bw[j] = (uint32_t)qweight[(size_t)(qrow0 + t * 8 + r) * N + gn];
        }
    };

    auto DEQ_STS = [&](int buf) {
        const uint32_t bbase = sb + B_BASE_OFF + (uint32_t)buf * B_BUF_STRIDE;
        #pragma unroll
        for (int j = 0; j < 4; ++j) {
            const int r = krB + 2 * j;
            const uint32_t w = bw[j];
            uint32_t o[4];
            // dual-nibble extraction: pairs (k0,k4),(k1,k5),(k2,k6),(k3,k7)
            // A is stored with the matching permutation, so positions align.
            o[0] = lop3_nib(w);
            o[1] = lop3_nib(w >> 4);
            o[2] = lop3_nib(w >> 8);
            o[3] = lop3_nib(w >> 12);
            #pragma unroll
            for (int i = 0; i < 4; ++i) {
                __half2 q2 = *reinterpret_cast<__half2*>(&o[i]);
                __half2 w2 = __hmul2(__hsub2(q2, z2), s2);  // (q-z) exact
                o[i] = *reinterpret_cast<uint32_t*>(&w2);
            }
            const uint32_t off = SWZ((uint32_t)(lnB * 128 + r * 16));
            STS128(bbase + off, o[0], o[1], o[2], o[3]);
        }
    };

    auto COMPUTE = [&](int buf) {
        const uint32_t abase = sb + (uint32_t)buf * A_BUF_STRIDE;
        const uint32_t bbase = sb + B_BASE_OFF + (uint32_t)buf * B_BUF_STRIDE;
        #pragma unroll
        for (int ks = 0; ks < 4; ++ks) {
            const uint32_t akb = (uint32_t)(ks * 32);
            uint32_t a[2][4], b[2][4];
            ldsm4(a[0], abase + SWZ(aOff0 + akb));
            ldsm4(a[1], abase + SWZ(aOff0 + 2048 + akb));   // +16 m rows
            ldsm4(b[0], bbase + SWZ(bOff0 + akb));
            ldsm4(b[1], bbase + SWZ(bOff0 + 2048 + akb));   // +16 n cols
            #pragma unroll
            for (int mi = 0; mi < 2; ++mi) {
                #pragma unroll
                for (int p = 0; p < 2; ++p) {
                    mma16816(c[mi][2 * p + 0], a[mi], b[p][0], b[p][1]);
                    mma16816(c[mi][2 * p + 1], a[mi], b[p][2], b[p][3]);
                }
            }
        }
    };

    // -------- pipeline --------
    ISSUE_A(0, 0);
    LOAD_B(0);
    DEQ_STS(0);
    CP_WAIT0();
    __syncthreads();

    for (int t = 0; t < NITER; ++t) {
        const int cur = t & 1;
        if (t + 1 < NITER) {
            ISSUE_A(t + 1, cur ^ 1);
            LOAD_B(t + 1);
        }
        COMPUTE(cur);
        if (t + 1 < NITER) {
            DEQ_STS(cur ^ 1);
            CP_WAIT0();
        }
        __syncthreads();
    }

    // -------- epilogue: atomic accumulate into out (bias preloaded) --------
    const int q  = lane >> 2;   // 0..7
    const int r2 = lane & 3;    // 0..3
    #pragma unroll
    for (int mi = 0; mi < 2; ++mi) {
        const int row0 = m0 + mw * 32 + mi * 16 + q;
        #pragma unroll
        for (int nj = 0; nj < 4; ++nj) {
            const int col = n0 + nw * 32 + nj * 8 + 2 * r2;
            float* p0 = out + (size_t)row0 * N + col;
            float* p1 = out + (size_t)(row0 + 8) * N + col;
            atomicAdd(p0,     c[mi][nj][0]);
            atomicAdd(p0 + 1, c[mi][nj][1]);
            atomicAdd(p1,     c[mi][nj][2]);
            atomicAdd(p1 + 1, c[mi][nj][3]);
        }
    }
}

// ======================= launch =======================

extern "C" void kernel_launch(void* const* d_in, const int* in_sizes, int n_in,
                              void* d_out, int out_size) {
    const float* x       = (const float*)d_in[0];
    const int*   qweight = (const int*)d_in[1];
    const int*   qzeros  = (const int*)d_in[2];
    const float* scales  = (const float*)d_in[3];
    const float* bias    = (const float*)d_in[4];
    // d_in[5] = g_idx: arange(K)//128 for this problem; group = k/GS hardcoded.
    float* out = (float*)d_out;

    cudaFuncSetAttribute(quantlinear_kernel,
                         cudaFuncAttributeMaxDynamicSharedMemorySize, SMEM_BYTES);

    convert_x_kernel<<<(M * K / 8 + 255) / 256, 256>>>(x);
    {
        dim3 gi((N / 4 + 255) / 256, M);
        init_out_kernel<<<gi, 256>>>(bias, out);
    }
    dim3 grid(NBLK_N, NBLK_M, KSPLIT);
    quantlinear_kernel<<<grid, THREADS, SMEM_BYTES>>>(qweight, qzeros, scales, out);
}